// round 3
// baseline (speedup 1.0000x reference)
#include <cuda_runtime.h>
#include <cuda_bf16.h>
#include <cstddef>

#define NN   50000
#define EE   800000
#define INC  128
#define OUTC 256
#define HALF 128
#define NR   6
#define NB   (NN * NR)            // 300000 buckets (node, rel)
#define NBLK ((NB + 4095) / 4096) // 74 scan blocks

// ---------------- scratch (module-scope device memory; no allocations) ------
__device__ float d_h1 [(size_t)NN * OUTC];
__device__ float d_h2 [(size_t)NN * OUTC];
__device__ float d_g1 [(size_t)NN * OUTC];
__device__ float d_g2 [(size_t)NN * OUTC];
__device__ float d_acc[(size_t)NN * NR * OUTC];   // per-(node,rel) means
__device__ int   d_cnt[NB];
__device__ int   d_off[NB];
__device__ int   d_cur[NB];
__device__ int   d_csr[EE];
__device__ int   d_bsum[128];
__device__ float d_inv[NB];
__device__ float d_wc1[(size_t)(NR + 1) * INC  * OUTC];   // [root1; W1]  896 x 256
__device__ float d_wc2[(size_t)(NR + 1) * OUTC * OUTC];   // [root2; W2] 1792 x 256
__device__ float d_wc3[(size_t)(NR + 1) * OUTC * HALF];   // [root3; W3] 1792 x 128

// ---------------- CSR build --------------------------------------------------
__global__ void count_k(const int* __restrict__ dst, const int* __restrict__ et,
                        int E, int* __restrict__ cnt)
{
    int e = blockIdx.x * blockDim.x + threadIdx.x;
    if (e < E) atomicAdd(&cnt[dst[e] * NR + et[e]], 1);
}

__global__ void inv_k(const int* __restrict__ cnt, float* __restrict__ inv, int n)
{
    int i = blockIdx.x * blockDim.x + threadIdx.x;
    if (i < n) {
        int c = cnt[i];
        inv[i] = 1.0f / (float)(c > 1 ? c : 1);
    }
}

// scan pass 1: per-4096-element block sums (each thread sums one int4)
__global__ void scan1_k(const int* __restrict__ cnt, int* __restrict__ bsum)
{
    __shared__ int sh[1024];
    int t = threadIdx.x;
    int i4 = blockIdx.x * 1024 + t;
    int s = 0;
    if (i4 * 4 < NB) {
        int4 v = ((const int4*)cnt)[i4];
        s = v.x + v.y + v.z + v.w;
    }
    sh[t] = s; __syncthreads();
    for (int o = 512; o > 0; o >>= 1) {
        if (t < o) sh[t] += sh[t + o];
        __syncthreads();
    }
    if (t == 0) bsum[blockIdx.x] = sh[0];
}

// scan pass 2: exclusive scan of <=128 block sums (single block)
__global__ void scan2_k(int* __restrict__ bsum, int n)
{
    __shared__ int sh[128];
    int t = threadIdx.x;
    int v = (t < n) ? bsum[t] : 0;
    sh[t] = v; __syncthreads();
    for (int o = 1; o < 128; o <<= 1) {
        int u = (t >= o) ? sh[t - o] : 0;
        __syncthreads();
        sh[t] += u;
        __syncthreads();
    }
    if (t < n) bsum[t] = sh[t] - v;   // exclusive
}

// scan pass 3: per-element exclusive offsets
__global__ void scan3_k(const int* __restrict__ cnt, const int* __restrict__ bsum,
                        int* __restrict__ off)
{
    __shared__ int sh[1024];
    int t = threadIdx.x;
    int i4 = blockIdx.x * 1024 + t;
    int4 v = make_int4(0, 0, 0, 0);
    bool ok = (i4 * 4 < NB);
    if (ok) v = ((const int4*)cnt)[i4];
    int s = v.x + v.y + v.z + v.w;
    sh[t] = s; __syncthreads();
    for (int o = 1; o < 1024; o <<= 1) {
        int u = (t >= o) ? sh[t - o] : 0;
        __syncthreads();
        sh[t] += u;
        __syncthreads();
    }
    int ex = bsum[blockIdx.x] + sh[t] - s;
    if (ok) {
        int4 w;
        w.x = ex;
        w.y = ex + v.x;
        w.z = ex + v.x + v.y;
        w.w = ex + v.x + v.y + v.z;
        ((int4*)off)[i4] = w;
    }
}

__global__ void fill_k(const int* __restrict__ src, const int* __restrict__ dst,
                       const int* __restrict__ et, int E,
                       const int* __restrict__ off, int* __restrict__ cur,
                       int* __restrict__ csr)
{
    int e = blockIdx.x * blockDim.x + threadIdx.x;
    if (e < E) {
        int k = dst[e] * NR + et[e];
        int p = off[k] + atomicAdd(&cur[k], 1);
        csr[p] = src[e];
    }
}

// ---------------- mean aggregation: one warp per (node, rel) bucket ----------
// acc[(node*NR+rel)*D + :] = inv[bucket] * sum_{e in bucket} xf[csr[e]][:]
template<int D>
__global__ void __launch_bounds__(256)
agg_k(const float* __restrict__ xf,
      const int* __restrict__ off, const int* __restrict__ cnt,
      const float* __restrict__ inv, const int* __restrict__ csr,
      float* __restrict__ acc)
{
    int w    = (int)(((size_t)blockIdx.x * blockDim.x + threadIdx.x) >> 5);
    int lane = threadIdx.x & 31;
    if (w >= NB) return;
    int o = off[w], c = cnt[w];
    constexpr int NV = D / 128;          // float4 per lane: 1 (D=128) or 2 (D=256)
    float4 a[NV];
#pragma unroll
    for (int v = 0; v < NV; v++) a[v] = make_float4(0.f, 0.f, 0.f, 0.f);
    for (int e = 0; e < c; e++) {
        int s = __ldg(&csr[o + e]);
        const float4* xs = (const float4*)(xf + (size_t)s * D);
#pragma unroll
        for (int v = 0; v < NV; v++) {
            float4 t = __ldg(&xs[lane + 32 * v]);
            a[v].x += t.x; a[v].y += t.y; a[v].z += t.z; a[v].w += t.w;
        }
    }
    float sc = inv[w];
    float4* p = (float4*)(acc + (size_t)w * D);
#pragma unroll
    for (int v = 0; v < NV; v++) {
        a[v].x *= sc; a[v].y *= sc; a[v].z *= sc; a[v].w *= sc;
        p[lane + 32 * v] = a[v];
    }
}

// ---------------- fp32 SGEMM: C = [A0 | A1] * B + bias (optional relu) ------
// A is a logical [M x K] row-major matrix: columns [0,d0) come from A0 (ld0),
// columns [d0,K) from A1 (ld1). K % 16 == 0, d0 % 16 == 0, Bld % 128 == 0.
// 128x128 block tile, 256 threads, 8x8 per thread, BK=16.
__global__ void __launch_bounds__(256)
gemm_k(const float* __restrict__ A0, const float* __restrict__ A1,
       int d0, int ld0, int ld1,
       const float* __restrict__ B, const float* __restrict__ bias,
       float* __restrict__ C, int ldc,
       int M, int K, int Bld, int relu)
{
    __shared__ float As[16][132];
    __shared__ float Bs[16][128];
    const int tid  = threadIdx.x;
    const int row0 = blockIdx.y * 128;
    const int col0 = blockIdx.x * 128;
    const int tx = tid & 15, ty = tid >> 4;

    float acc[8][8];
#pragma unroll
    for (int i = 0; i < 8; i++)
#pragma unroll
        for (int j = 0; j < 8; j++) acc[i][j] = 0.f;

    for (int k0 = 0; k0 < K; k0 += 16) {
        const float* Ab; int ld, kk;
        if (k0 < d0) { Ab = A0; ld = ld0; kk = k0; }
        else         { Ab = A1; ld = ld1; kk = k0 - d0; }
#pragma unroll
        for (int j = 0; j < 2; j++) {
            int idx = tid + j * 256;          // 512 float4 loads of the A tile
            int ar  = idx >> 2, kq = idx & 3;
            int gr  = row0 + ar;
            float4 v = make_float4(0.f, 0.f, 0.f, 0.f);
            if (gr < M) v = *(const float4*)(Ab + (size_t)gr * ld + kk + kq * 4);
            As[kq * 4 + 0][ar] = v.x;
            As[kq * 4 + 1][ar] = v.y;
            As[kq * 4 + 2][ar] = v.z;
            As[kq * 4 + 3][ar] = v.w;
        }
#pragma unroll
        for (int j = 0; j < 2; j++) {
            int idx = tid + j * 256;          // 512 float4 loads of the B tile
            int bk  = idx >> 5, bn = (idx & 31) * 4;
            *(float4*)&Bs[bk][bn] =
                *(const float4*)(B + (size_t)(k0 + bk) * Bld + col0 + bn);
        }
        __syncthreads();
#pragma unroll
        for (int k = 0; k < 16; k++) {
            float ra[8], rb[8];
            *(float4*)&ra[0] = *(const float4*)&As[k][ty * 8];
            *(float4*)&ra[4] = *(const float4*)&As[k][ty * 8 + 4];
            *(float4*)&rb[0] = *(const float4*)&Bs[k][tx * 8];
            *(float4*)&rb[4] = *(const float4*)&Bs[k][tx * 8 + 4];
#pragma unroll
            for (int i = 0; i < 8; i++)
#pragma unroll
                for (int j = 0; j < 8; j++)
                    acc[i][j] += ra[i] * rb[j];
        }
        __syncthreads();
    }

#pragma unroll
    for (int i = 0; i < 8; i++) {
        int gr = row0 + ty * 8 + i;
        if (gr < M) {
#pragma unroll
            for (int j = 0; j < 8; j += 4) {
                int gc = col0 + tx * 8 + j;
                float4 v;
                v.x = acc[i][j + 0] + bias[gc + 0];
                v.y = acc[i][j + 1] + bias[gc + 1];
                v.z = acc[i][j + 2] + bias[gc + 2];
                v.w = acc[i][j + 3] + bias[gc + 3];
                if (relu) {
                    v.x = fmaxf(v.x, 0.f); v.y = fmaxf(v.y, 0.f);
                    v.z = fmaxf(v.z, 0.f); v.w = fmaxf(v.w, 0.f);
                }
                *(float4*)(C + (size_t)gr * ldc + gc) = v;
            }
        }
    }
}

// ---------------- launch ------------------------------------------------------
extern "C" void kernel_launch(void* const* d_in, const int* in_sizes, int n_in,
                              void* d_out, int out_size)
{
    const float* x       = (const float*)d_in[0];
    const int*   eidx    = (const int*)  d_in[1];
    const int*   etype   = (const int*)  d_in[2];
    const float* enc_w0  = (const float*)d_in[3];
    const float* enc_b0  = (const float*)d_in[4];
    const float* enc_w1  = (const float*)d_in[5];
    const float* enc_b1  = (const float*)d_in[6];
    const float* enc_w2  = (const float*)d_in[7];
    const float* enc_b2  = (const float*)d_in[8];
    const float* W1      = (const float*)d_in[9];
    const float* root1   = (const float*)d_in[10];
    const float* b1      = (const float*)d_in[11];
    const float* W2      = (const float*)d_in[12];
    const float* root2   = (const float*)d_in[13];
    const float* b2      = (const float*)d_in[14];
    const float* W3      = (const float*)d_in[15];
    const float* root3   = (const float*)d_in[16];
    const float* b3      = (const float*)d_in[17];
    float* out = (float*)d_out;

    const int N = NN, E = EE;
    const int* src = eidx;
    const int* dst = eidx + E;

    float *h1, *h2, *g1, *g2, *acc, *inv, *wc1, *wc2, *wc3;
    int *cnt, *off, *cur, *csr, *bsum;
    cudaGetSymbolAddress((void**)&h1,   d_h1);
    cudaGetSymbolAddress((void**)&h2,   d_h2);
    cudaGetSymbolAddress((void**)&g1,   d_g1);
    cudaGetSymbolAddress((void**)&g2,   d_g2);
    cudaGetSymbolAddress((void**)&acc,  d_acc);
    cudaGetSymbolAddress((void**)&cnt,  d_cnt);
    cudaGetSymbolAddress((void**)&off,  d_off);
    cudaGetSymbolAddress((void**)&cur,  d_cur);
    cudaGetSymbolAddress((void**)&csr,  d_csr);
    cudaGetSymbolAddress((void**)&bsum, d_bsum);
    cudaGetSymbolAddress((void**)&inv,  d_inv);
    cudaGetSymbolAddress((void**)&wc1,  d_wc1);
    cudaGetSymbolAddress((void**)&wc2,  d_wc2);
    cudaGetSymbolAddress((void**)&wc3,  d_wc3);

    // ---- CSR build (edge structure; shared by all three conv layers) ----
    cudaMemsetAsync(cnt, 0, (size_t)NB * sizeof(int));
    cudaMemsetAsync(cur, 0, (size_t)NB * sizeof(int));
    count_k<<<(E + 255) / 256, 256>>>(dst, etype, E, cnt);
    inv_k<<<(NB + 255) / 256, 256>>>(cnt, inv, NB);
    scan1_k<<<NBLK, 1024>>>(cnt, bsum);
    scan2_k<<<1, 128>>>(bsum, NBLK);
    scan3_k<<<NBLK, 1024>>>(cnt, bsum, off);
    fill_k<<<(E + 255) / 256, 256>>>(src, dst, etype, E, off, cur, csr);

    // stacked weights [root; W_0..W_5] (pure concatenation -> D2D copies)
    cudaMemcpyAsync(wc1,              root1, (size_t)INC  * OUTC * 4,      cudaMemcpyDeviceToDevice);
    cudaMemcpyAsync(wc1 + INC * OUTC, W1,    (size_t)NR * INC  * OUTC * 4, cudaMemcpyDeviceToDevice);
    cudaMemcpyAsync(wc2,               root2, (size_t)OUTC * OUTC * 4,      cudaMemcpyDeviceToDevice);
    cudaMemcpyAsync(wc2 + OUTC * OUTC, W2,    (size_t)NR * OUTC * OUTC * 4, cudaMemcpyDeviceToDevice);
    cudaMemcpyAsync(wc3,               root3, (size_t)OUTC * HALF * 4,      cudaMemcpyDeviceToDevice);
    cudaMemcpyAsync(wc3 + OUTC * HALF, W3,    (size_t)NR * OUTC * HALF * 4, cudaMemcpyDeviceToDevice);

    const dim3 blk(256);
    const int rowTiles  = (N + 127) / 128;
    const int aggBlocks = (int)(((size_t)NB * 32 + 255) / 256);

    // --- dense encoder branch: out[:, 0:128] ---
    gemm_k<<<dim3(2, rowTiles), blk>>>(x,  nullptr, INC,  INC,  0, enc_w0, enc_b0, h1,  OUTC, N, INC,  OUTC, 1);
    gemm_k<<<dim3(2, rowTiles), blk>>>(h1, nullptr, OUTC, OUTC, 0, enc_w1, enc_b1, h2,  OUTC, N, OUTC, OUTC, 1);
    gemm_k<<<dim3(1, rowTiles), blk>>>(h2, nullptr, OUTC, OUTC, 0, enc_w2, enc_b2, out, OUTC, N, OUTC, HALF, 0);

    // --- conv1: g1 = relu([x | mean_r(x)] @ [root1; W1] + b1), K = 896 ---
    agg_k<INC><<<aggBlocks, blk>>>(x, off, cnt, inv, csr, acc);
    gemm_k<<<dim3(2, rowTiles), blk>>>(x, acc, INC, INC, NR * INC, wc1, b1, g1, OUTC, N, (NR + 1) * INC, OUTC, 1);

    // --- conv2: g2 = relu([g1 | mean_r(g1)] @ [root2; W2] + b2), K = 1792 ---
    agg_k<OUTC><<<aggBlocks, blk>>>(g1, off, cnt, inv, csr, acc);
    gemm_k<<<dim3(2, rowTiles), blk>>>(g1, acc, OUTC, OUTC, NR * OUTC, wc2, b2, g2, OUTC, N, (NR + 1) * OUTC, OUTC, 1);

    // --- conv3: out[:, 128:256] = [g2 | mean_r(g2)] @ [root3; W3] + b3 ---
    agg_k<OUTC><<<aggBlocks, blk>>>(g2, off, cnt, inv, csr, acc);
    gemm_k<<<dim3(1, rowTiles), blk>>>(g2, acc, OUTC, OUTC, NR * OUTC, wc3, b3, out + HALF, OUTC, N, (NR + 1) * OUTC, HALF, 0);
}

// round 5
// speedup vs baseline: 2.0225x; 2.0225x over previous
#include <cuda_runtime.h>
#include <cuda_bf16.h>
#include <cstdint>
#include <cstddef>

#define NN   50000
#define EE   800000
#define INC  128
#define OUTC 256
#define HALF 128
#define NR   6

// ---------------- scratch (module-scope device memory; no allocations) ------
__device__ float d_h1 [(size_t)NN * OUTC];
__device__ float d_h2 [(size_t)NN * OUTC];
__device__ float d_g1 [(size_t)NN * OUTC];
__device__ float d_g2 [(size_t)NN * OUTC];
__device__ float d_acc[(size_t)NN * NR * OUTC];
__device__ int   d_cnt[NN * NR];
__device__ float d_inv[NN * NR];
__device__ float d_wc1[(size_t)(NR + 1) * INC  * OUTC];   // [root1; W1]  896 x 256
__device__ float d_wc2[(size_t)(NR + 1) * OUTC * OUTC];   // [root2; W2] 1792 x 256
__device__ float d_wc3[(size_t)(NR + 1) * OUTC * HALF];   // [root3; W3] 1792 x 128
// bf16 hi/lo weight pools, each matrix transposed to [N][K] row-major
// offsets: e0=0, e1=32768, e2=98304, c1=131072, c2=360448, c3=819200 (total 1M)
__device__ __nv_bfloat16 d_bh[1048576];
__device__ __nv_bfloat16 d_bl[1048576];

// ---------------- mma.sync helpers (sm_80+ family-wide; no sm_103a ISA) -----
__device__ __forceinline__ uint32_t smem_u32(const void* p) {
    uint32_t a;
    asm("{ .reg .u64 t; cvta.to.shared.u64 t, %1; cvt.u32.u64 %0, t; }" : "=r"(a) : "l"(p));
    return a;
}
__device__ __forceinline__ void ldsm4(uint32_t* r, uint32_t addr) {
    asm volatile("ldmatrix.sync.aligned.m8n8.x4.shared.b16 {%0,%1,%2,%3}, [%4];"
        : "=r"(r[0]), "=r"(r[1]), "=r"(r[2]), "=r"(r[3]) : "r"(addr));
}
__device__ __forceinline__ void mma16816(float* c, const uint32_t* a, const uint32_t* b) {
    asm volatile("mma.sync.aligned.m16n8k16.row.col.f32.bf16.bf16.f32 "
        "{%0,%1,%2,%3}, {%4,%5,%6,%7}, {%8,%9}, {%0,%1,%2,%3};"
        : "+f"(c[0]), "+f"(c[1]), "+f"(c[2]), "+f"(c[3])
        : "r"(a[0]), "r"(a[1]), "r"(a[2]), "r"(a[3]), "r"(b[0]), "r"(b[1]));
}

// ---------------- bf16x3 HMMA GEMM ------------------------------------------
// C[M x N] = [A0 | A1](fp32) * B^T + bias, B given pre-split/transposed as
// Bh/Bl bf16 [N][K] row-major.  A1 rows optionally scaled per 'drel'-wide
// column block by invp[row*NR + blk] (mean normalization folded in).
// Tile 128x128, 8 warps (4 M x 2 N), warp tile 32x64, BK=32.
#define LDA 40   // 32 + 8 pad elements (80B rows -> conflict-free ldmatrix)

__global__ void __launch_bounds__(256)
gemm_mma(const float* __restrict__ A0, const float* __restrict__ A1,
         int d0, int ld0, int ld1,
         const float* __restrict__ invp, int drel,
         const __nv_bfloat16* __restrict__ Bhg, const __nv_bfloat16* __restrict__ Blg,
         const float* __restrict__ bias, float* __restrict__ C, int ldc,
         int M, int K, int relu)
{
    __shared__ __align__(16) __nv_bfloat16 sAh[128 * LDA];
    __shared__ __align__(16) __nv_bfloat16 sAl[128 * LDA];
    __shared__ __align__(16) __nv_bfloat16 sBh[128 * LDA];
    __shared__ __align__(16) __nv_bfloat16 sBl[128 * LDA];

    const int tid  = threadIdx.x;
    const int lane = tid & 31;
    const int w    = tid >> 5;
    const int wm   = w & 3;           // 0..3 -> m offset 32*wm
    const int wn   = w >> 2;          // 0..1 -> n offset 64*wn
    const int row0 = blockIdx.y * 128;
    const int n0   = blockIdx.x * 128;

    const uint32_t sAhB = smem_u32(sAh);
    const uint32_t sAlB = smem_u32(sAl);
    const uint32_t sBhB = smem_u32(sBh);
    const uint32_t sBlB = smem_u32(sBl);

    float acc[2][8][4];
#pragma unroll
    for (int i = 0; i < 2; i++)
#pragma unroll
        for (int j = 0; j < 8; j++)
#pragma unroll
            for (int q = 0; q < 4; q++) acc[i][j][q] = 0.f;

    // ldmatrix lane-address components (bytes)
    const uint32_t aRow = (uint32_t)(lane & 15);            // m_local
    const uint32_t aKof = (uint32_t)((lane >> 4) * 8);      // k offset
    const uint32_t bRow = (uint32_t)((lane & 7) + ((lane >> 4) * 8));
    const uint32_t bKof = (uint32_t)(((lane >> 3) & 1) * 8);

    const int nIter = K / 32;
    for (int s = 0; s < nIter; s++) {
        if (s) __syncthreads();
        // ---- A chunk: 128 rows x 32 fp32 -> split bf16 hi/lo into smem ----
        {
            const float* Ab; int ld; int cb = s * 32;
            bool inA1 = (cb >= d0);
            if (!inA1) { Ab = A0; ld = ld0; } else { Ab = A1; ld = ld1; cb -= d0; }
            int rblk = inA1 ? (cb / drel) : 0;
#pragma unroll
            for (int j = 0; j < 4; j++) {
                int idx = tid + j * 256;      // 1024 float4
                int r = idx >> 3, q = idx & 7;
                int gr = row0 + r;
                float4 v = make_float4(0.f, 0.f, 0.f, 0.f);
                if (gr < M) {
                    v = *(const float4*)(Ab + (size_t)gr * ld + cb + q * 4);
                    if (inA1 && invp) {
                        float sc = invp[gr * NR + rblk];
                        v.x *= sc; v.y *= sc; v.z *= sc; v.w *= sc;
                    }
                }
                __nv_bfloat16 h0 = __float2bfloat16(v.x), h1 = __float2bfloat16(v.y);
                __nv_bfloat16 h2 = __float2bfloat16(v.z), h3 = __float2bfloat16(v.w);
                __nv_bfloat16 l0 = __float2bfloat16(v.x - __bfloat162float(h0));
                __nv_bfloat16 l1 = __float2bfloat16(v.y - __bfloat162float(h1));
                __nv_bfloat16 l2 = __float2bfloat16(v.z - __bfloat162float(h2));
                __nv_bfloat16 l3 = __float2bfloat16(v.w - __bfloat162float(h3));
                uint32_t o = (uint32_t)(r * 80 + q * 8);
                *(__nv_bfloat162*)((char*)sAh + o)     = {h0, h1};
                *(__nv_bfloat162*)((char*)sAh + o + 4) = {h2, h3};
                *(__nv_bfloat162*)((char*)sAl + o)     = {l0, l1};
                *(__nv_bfloat162*)((char*)sAl + o + 4) = {l2, l3};
            }
        }
        // ---- B chunk: 128 n-rows x 32 k bf16, hi and lo ----
        {
            const int kb = s * 32;
#pragma unroll
            for (int j = 0; j < 2; j++) {
                int idx = tid + j * 256;      // 512 uint4
                int r = idx >> 2, q = idx & 3;
                size_t go = (size_t)(n0 + r) * K + kb + q * 8;
                uint32_t o = (uint32_t)(r * 80 + q * 16);
                *(uint4*)((char*)sBh + o) = *(const uint4*)(Bhg + go);
                *(uint4*)((char*)sBl + o) = *(const uint4*)(Blg + go);
            }
        }
        __syncthreads();
        // ---- compute: 2 k16 steps x (3-pass bf16x3) ----
#pragma unroll
        for (int kk = 0; kk < 32; kk += 16) {
            uint32_t ah[2][4], al[2][4];
#pragma unroll
            for (int mi = 0; mi < 2; mi++) {
                uint32_t ao = (uint32_t)((wm * 32 + mi * 16 + aRow) * 80 + (kk + aKof) * 2);
                ldsm4(ah[mi], sAhB + ao);
                ldsm4(al[mi], sAlB + ao);
            }
#pragma unroll
            for (int j2 = 0; j2 < 4; j2++) {
                uint32_t bo = (uint32_t)((wn * 64 + j2 * 16 + bRow) * 80 + (kk + bKof) * 2);
                uint32_t bh[4], bl[4];
                ldsm4(bh, sBhB + bo);
                ldsm4(bl, sBlB + bo);
#pragma unroll
                for (int mi = 0; mi < 2; mi++)
#pragma unroll
                    for (int nj = 0; nj < 2; nj++) {
                        float* c = acc[mi][j2 * 2 + nj];
                        mma16816(c, ah[mi], bh + nj * 2);
                        mma16816(c, al[mi], bh + nj * 2);
                        mma16816(c, ah[mi], bl + nj * 2);
                    }
            }
        }
    }

    // ---- epilogue: regs -> gmem with bias (+relu) ----
    const int g  = lane >> 2;
    const int tg = lane & 3;
#pragma unroll
    for (int mi = 0; mi < 2; mi++) {
        int r0 = row0 + wm * 32 + mi * 16 + g;
#pragma unroll
        for (int j = 0; j < 8; j++) {
            int gc = n0 + wn * 64 + j * 8 + tg * 2;
            float b0 = bias[gc], b1 = bias[gc + 1];
            float2 v0 = make_float2(acc[mi][j][0] + b0, acc[mi][j][1] + b1);
            float2 v1 = make_float2(acc[mi][j][2] + b0, acc[mi][j][3] + b1);
            if (relu) {
                v0.x = fmaxf(v0.x, 0.f); v0.y = fmaxf(v0.y, 0.f);
                v1.x = fmaxf(v1.x, 0.f); v1.y = fmaxf(v1.y, 0.f);
            }
            if (r0 < M)     *(float2*)(C + (size_t)r0 * ldc + gc)       = v0;
            if (r0 + 8 < M) *(float2*)(C + (size_t)(r0 + 8) * ldc + gc) = v1;
        }
    }
}

// ---------------- weight convert: B fp32 [K][N] -> hi/lo bf16 [N][K] --------
__global__ void convw_k(const float* __restrict__ B, int K, int N,
                        __nv_bfloat16* __restrict__ bh, __nv_bfloat16* __restrict__ bl)
{
    int idx = blockIdx.x * blockDim.x + threadIdx.x;
    if (idx >= N * K) return;
    int n = idx / K, k = idx % K;
    float v = B[(size_t)k * N + n];
    __nv_bfloat16 hi = __float2bfloat16(v);
    __nv_bfloat16 lo = __float2bfloat16(v - __bfloat162float(hi));
    bh[idx] = hi;
    bl[idx] = lo;
}

// ---------------- aggregation (round-2 measured path) ------------------------
__global__ void count_k(const int* __restrict__ dst, const int* __restrict__ et,
                        int E, int* __restrict__ cnt)
{
    int e = blockIdx.x * blockDim.x + threadIdx.x;
    if (e < E) atomicAdd(&cnt[dst[e] * NR + et[e]], 1);
}
__global__ void inv_k(const int* __restrict__ cnt, float* __restrict__ inv, int n)
{
    int i = blockIdx.x * blockDim.x + threadIdx.x;
    if (i < n) { int c = cnt[i]; inv[i] = 1.0f / (float)(c > 1 ? c : 1); }
}
__global__ void scatter_k(const float* __restrict__ xf, int d,
                          const int* __restrict__ src, const int* __restrict__ dst,
                          const int* __restrict__ et, int E,
                          float* __restrict__ acc, int accld)
{
    int w    = (int)(((size_t)blockIdx.x * blockDim.x + threadIdx.x) >> 5);
    int lane = threadIdx.x & 31;
    if (w >= E) return;
    int s = src[w], t = dst[w], r = et[w];
    const float4* xs = (const float4*)(xf + (size_t)s * d);
    float4*       a  = (float4*)(acc + (size_t)t * accld + r * d);
    int n4 = d >> 2;
    for (int i = lane; i < n4; i += 32)
        atomicAdd(&a[i], xs[i]);
}

// ---------------- launch ------------------------------------------------------
extern "C" void kernel_launch(void* const* d_in, const int* in_sizes, int n_in,
                              void* d_out, int out_size)
{
    const float* x      = (const float*)d_in[0];
    const int*   eidx   = (const int*)  d_in[1];
    const int*   etype  = (const int*)  d_in[2];
    const float* enc_w0 = (const float*)d_in[3];
    const float* enc_b0 = (const float*)d_in[4];
    const float* enc_w1 = (const float*)d_in[5];
    const float* enc_b1 = (const float*)d_in[6];
    const float* enc_w2 = (const float*)d_in[7];
    const float* enc_b2 = (const float*)d_in[8];
    const float* W1     = (const float*)d_in[9];
    const float* root1  = (const float*)d_in[10];
    const float* b1     = (const float*)d_in[11];
    const float* W2     = (const float*)d_in[12];
    const float* root2  = (const float*)d_in[13];
    const float* b2     = (const float*)d_in[14];
    const float* W3     = (const float*)d_in[15];
    const float* root3  = (const float*)d_in[16];
    const float* b3     = (const float*)d_in[17];
    float* out = (float*)d_out;

    const int N = NN, E = EE;
    const int* src = eidx;
    const int* dst = eidx + E;

    float *h1, *h2, *g1, *g2, *acc, *inv, *wc1, *wc2, *wc3;
    int* cnt;
    __nv_bfloat16 *bh, *bl;
    cudaGetSymbolAddress((void**)&h1,  d_h1);
    cudaGetSymbolAddress((void**)&h2,  d_h2);
    cudaGetSymbolAddress((void**)&g1,  d_g1);
    cudaGetSymbolAddress((void**)&g2,  d_g2);
    cudaGetSymbolAddress((void**)&acc, d_acc);
    cudaGetSymbolAddress((void**)&cnt, d_cnt);
    cudaGetSymbolAddress((void**)&inv, d_inv);
    cudaGetSymbolAddress((void**)&wc1, d_wc1);
    cudaGetSymbolAddress((void**)&wc2, d_wc2);
    cudaGetSymbolAddress((void**)&wc3, d_wc3);
    cudaGetSymbolAddress((void**)&bh,  d_bh);
    cudaGetSymbolAddress((void**)&bl,  d_bl);

    // bf16 pool offsets (elements)
    const int K1 = (NR + 1) * INC;    // 896
    const int K2 = (NR + 1) * OUTC;   // 1792
    const size_t oE0 = 0;                       // enc_w0: N=256, K=128
    const size_t oE1 = oE0 + (size_t)OUTC * INC;    // enc_w1: N=256, K=256
    const size_t oE2 = oE1 + (size_t)OUTC * OUTC;   // enc_w2: N=128, K=256
    const size_t oC1 = oE2 + (size_t)HALF * OUTC;   // wc1:   N=256, K=896
    const size_t oC2 = oC1 + (size_t)OUTC * K1;     // wc2:   N=256, K=1792
    const size_t oC3 = oC2 + (size_t)OUTC * K2;     // wc3:   N=128, K=1792

    // degree counts (shared by all conv layers)
    cudaMemsetAsync(cnt, 0, (size_t)NR * N * sizeof(int));
    count_k<<<(E + 255) / 256, 256>>>(dst, etype, E, cnt);
    inv_k<<<(NR * N + 255) / 256, 256>>>(cnt, inv, NR * N);

    // stacked conv weights, then split/transpose all 6 weight matrices
    cudaMemcpyAsync(wc1,               root1, (size_t)INC  * OUTC * 4,      cudaMemcpyDeviceToDevice);
    cudaMemcpyAsync(wc1 + INC * OUTC,  W1,    (size_t)NR * INC  * OUTC * 4, cudaMemcpyDeviceToDevice);
    cudaMemcpyAsync(wc2,               root2, (size_t)OUTC * OUTC * 4,      cudaMemcpyDeviceToDevice);
    cudaMemcpyAsync(wc2 + OUTC * OUTC, W2,    (size_t)NR * OUTC * OUTC * 4, cudaMemcpyDeviceToDevice);
    cudaMemcpyAsync(wc3,               root3, (size_t)OUTC * HALF * 4,      cudaMemcpyDeviceToDevice);
    cudaMemcpyAsync(wc3 + OUTC * HALF, W3,    (size_t)NR * OUTC * HALF * 4, cudaMemcpyDeviceToDevice);

    convw_k<<<(OUTC * INC  + 255) / 256, 256>>>(enc_w0, INC,  OUTC, bh + oE0, bl + oE0);
    convw_k<<<(OUTC * OUTC + 255) / 256, 256>>>(enc_w1, OUTC, OUTC, bh + oE1, bl + oE1);
    convw_k<<<(HALF * OUTC + 255) / 256, 256>>>(enc_w2, OUTC, HALF, bh + oE2, bl + oE2);
    convw_k<<<(OUTC * K1 + 255) / 256, 256>>>(wc1, K1, OUTC, bh + oC1, bl + oC1);
    convw_k<<<(OUTC * K2 + 255) / 256, 256>>>(wc2, K2, OUTC, bh + oC2, bl + oC2);
    convw_k<<<(HALF * K2 + 255) / 256, 256>>>(wc3, K2, HALF, bh + oC3, bl + oC3);

    const dim3 blk(256);
    const int rowTiles   = (N + 127) / 128;   // 391
    const int scatBlocks = (int)(((size_t)E * 32 + 255) / 256);

    // --- dense encoder branch: out[:, 0:128] ---
    gemm_mma<<<dim3(2, rowTiles), blk>>>(x,  nullptr, INC,  INC,  0, nullptr, 1,
                                         bh + oE0, bl + oE0, enc_b0, h1,  OUTC, N, INC,  1);
    gemm_mma<<<dim3(2, rowTiles), blk>>>(h1, nullptr, OUTC, OUTC, 0, nullptr, 1,
                                         bh + oE1, bl + oE1, enc_b1, h2,  OUTC, N, OUTC, 1);
    gemm_mma<<<dim3(1, rowTiles), blk>>>(h2, nullptr, OUTC, OUTC, 0, nullptr, 1,
                                         bh + oE2, bl + oE2, enc_b2, out, OUTC, N, OUTC, 0);

    // --- conv1: g1 = relu([x | mean_r(x)] @ [root1; W1] + b1), K = 896 ---
    cudaMemsetAsync(acc, 0, (size_t)N * NR * INC * 4);
    scatter_k<<<scatBlocks, blk>>>(x, INC, src, dst, etype, E, acc, NR * INC);
    gemm_mma<<<dim3(2, rowTiles), blk>>>(x, acc, INC, INC, NR * INC, inv, INC,
                                         bh + oC1, bl + oC1, b1, g1, OUTC, N, K1, 1);

    // --- conv2: g2 = relu([g1 | mean_r(g1)] @ [root2; W2] + b2), K = 1792 ---
    cudaMemsetAsync(acc, 0, (size_t)N * NR * OUTC * 4);
    scatter_k<<<scatBlocks, blk>>>(g1, OUTC, src, dst, etype, E, acc, NR * OUTC);
    gemm_mma<<<dim3(2, rowTiles), blk>>>(g1, acc, OUTC, OUTC, NR * OUTC, inv, OUTC,
                                         bh + oC2, bl + oC2, b2, g2, OUTC, N, K2, 1);

    // --- conv3: out[:, 128:256] = [g2 | mean_r(g2)] @ [root3; W3] + b3 ---
    cudaMemsetAsync(acc, 0, (size_t)N * NR * OUTC * 4);
    scatter_k<<<scatBlocks, blk>>>(g2, OUTC, src, dst, etype, E, acc, NR * OUTC);
    gemm_mma<<<dim3(1, rowTiles), blk>>>(g2, acc, OUTC, OUTC, NR * OUTC, inv, OUTC,
                                         bh + oC3, bl + oC3, b3, out + HALF, OUTC, N, K2, 0);
}